// round 8
// baseline (speedup 1.0000x reference)
#include <cuda_runtime.h>
#include <cuda_fp16.h>
#include <cstdint>

// ---------------------------------------------------------------------------
// FermiLayer: N=512 (256 up / 256 dn), SINGLE=256, PAIR=128
// inputs: [0] h_one (512,256) [1] h_two (512,512,128) [2] W1 (512,256)
//         [3] b1 (256) [4] Wg (512,256) [5] W2 (128,128) [6] b2 (128)
// output: [h_one_out | h_two_out] fp32
// k_two: fp16 mma.sync, 2-pass exact-A split (D = A*Wh), B-frags hoisted
// across passes. g2 partials fused into k_two; k_one folds g2/gt combines.
// ---------------------------------------------------------------------------

#define GAIN    1.5927812698663017f
#define RSQRT2  0.7071067811865475f
#define INV256  0.00390625f

typedef unsigned long long u64;
typedef unsigned int u32;

// scratch (__device__ globals: allocation-free rule)
__device__ float g_g2p[4 * 2 * 512 * 128];  // [q][s][j][p] partial sums
__device__ float g_g1[512];
__device__ float g_gtp[4 * 256];            // gt partials (4 k-chunks)
// W2^T fp16 in padded [n][k] layout (row stride 272B)
__device__ __align__(16) unsigned char g_w2h[35840];

__device__ __forceinline__ float tanh_fast(float x) {
    float y;
    asm("tanh.approx.f32 %0, %1;" : "=f"(y) : "f"(x));
    return y;
}
__device__ __forceinline__ u32 smem_u32(const void* p) {
    u32 a;
    asm("{ .reg .u64 t; cvta.to.shared.u64 t, %1; cvt.u32.u64 %0, t; }" : "=r"(a) : "l"(p));
    return a;
}
__device__ __forceinline__ void ldsm4(u32* r, u32 addr) {
    asm volatile("ldmatrix.sync.aligned.m8n8.x4.shared.b16 {%0,%1,%2,%3}, [%4];"
                 : "=r"(r[0]), "=r"(r[1]), "=r"(r[2]), "=r"(r[3]) : "r"(addr));
}
__device__ __forceinline__ void mma16816(float* c, const u32* a, const u32* b) {
    asm volatile(
        "mma.sync.aligned.m16n8k16.row.col.f32.f16.f16.f32 "
        "{%0,%1,%2,%3}, {%4,%5,%6,%7}, {%8,%9}, {%0,%1,%2,%3};"
        : "+f"(c[0]), "+f"(c[1]), "+f"(c[2]), "+f"(c[3])
        : "r"(a[0]), "r"(a[1]), "r"(a[2]), "r"(a[3]), "r"(b[0]), "r"(b[1]));
}
__device__ __forceinline__ void split2h(float e0, float e1, u32& hp, u32& lp) {
    __half2 h = __float22half2_rn(make_float2(e0, e1));
    float2 hf = __half22float2(h);
    __half2 l = __float22half2_rn(make_float2(e0 - hf.x, e1 - hf.y));
    hp = *(u32*)&h;
    lp = *(u32*)&l;
}
__device__ __forceinline__ void split4h(const float4& v, u64& hp, u64& lp) {
    u32 h0, l0, h1, l1;
    split2h(v.x, v.y, h0, l0);
    split2h(v.z, v.w, h1, l1);
    hp = (u64)h0 | ((u64)h1 << 32);
    lp = (u64)l0 | ((u64)l1 << 32);
}

// ---------------------------------------------------------------------------
__global__ void k_g1(const float* __restrict__ h_one) {
    int s = blockIdx.x, c = threadIdx.x;
    const float* p = h_one + (size_t)s * 65536 + c;
    float sum = 0.f;
#pragma unroll 8
    for (int r = 0; r < 256; r++) sum += p[r * 256];
    g_g1[s * 256 + c] = sum * INV256;
}

// gt partials: block q covers k in [q*128, q*128+128)
__global__ void k_gtp(const float* __restrict__ Wg) {
    __shared__ float s_g1[128];
    int q = blockIdx.x;
    int c = threadIdx.x;
    if (c < 128) s_g1[c] = g_g1[q * 128 + c];
    __syncthreads();
    float acc = 0.f;
#pragma unroll 4
    for (int kb = 0; kb < 16; kb++) {
        float w[8];
#pragma unroll
        for (int i = 0; i < 8; i++) w[i] = Wg[(q * 128 + kb * 8 + i) * 256 + c];
#pragma unroll
        for (int i = 0; i < 8; i++) acc += s_g1[kb * 8 + i] * w[i];
    }
    g_gtp[q * 256 + c] = acc;
}

// ---------------------------------------------------------------------------
// K2: h_one path. 64 blocks x 256 threads, 8 rows/block.
// Folds g2 partial combine (4 chunks) and gt combine (+b1) into staging.
// ---------------------------------------------------------------------------
__global__ void __launch_bounds__(256)
k_one(const float* __restrict__ h_one,
      const float* __restrict__ W1,
      const float* __restrict__ b1,
      float* __restrict__ out_one) {
    __shared__ float s_in[4096];   // [k][r], k=0..511, r=0..7
    int tid = threadIdx.x;
    int r0 = blockIdx.x * 8;
#pragma unroll
    for (int i = 0; i < 16; i++) {
        int e = tid + i * 256;     // 0..4095
        int k = e >> 3;
        int r = e & 7;
        int n = r0 + r;
        float v;
        if (k < 256) {
            v = h_one[n * 256 + k];
        } else {
            int sp = (k < 384) ? 0 : 1;
            int p = k - 256 - sp * 128;
            size_t base = (size_t)sp * 65536 + (size_t)n * 128 + p;
            v = (g_g2p[base] + g_g2p[base + 131072] +
                 g_g2p[base + 262144] + g_g2p[base + 393216]) * INV256;
        }
        s_in[k * 8 + r] = v;
    }
    __syncthreads();

    int c = tid;
    float acc[8];
#pragma unroll
    for (int r = 0; r < 8; r++) acc[r] = 0.f;
#pragma unroll 2
    for (int kb = 0; kb < 64; kb++) {
        float w[8];
#pragma unroll
        for (int i = 0; i < 8; i++) w[i] = W1[(kb * 8 + i) * 256 + c];
#pragma unroll
        for (int i = 0; i < 8; i++) {
            const float4* s4 = (const float4*)(s_in + (kb * 8 + i) * 8);
            float4 a0 = s4[0], a1 = s4[1];
            acc[0] += a0.x * w[i];
            acc[1] += a0.y * w[i];
            acc[2] += a0.z * w[i];
            acc[3] += a0.w * w[i];
            acc[4] += a1.x * w[i];
            acc[5] += a1.y * w[i];
            acc[6] += a1.z * w[i];
            acc[7] += a1.w * w[i];
        }
    }
    float gt = b1[c] + g_gtp[c] + g_gtp[256 + c] + g_gtp[512 + c] + g_gtp[768 + c];
#pragma unroll
    for (int r = 0; r < 8; r++) {
        float pre = (acc[r] + gt) * RSQRT2;
        out_one[(r0 + r) * 256 + c] = (s_in[c * 8 + r] + GAIN * tanh_fast(pre)) * RSQRT2;
    }
}

// ---------------------------------------------------------------------------
// W2 prep: W2T[n][k] = fp16(W2[k][n]), padded rows (272B stride).
// ---------------------------------------------------------------------------
#define BSTRIDE 272

__global__ void k_w2prep(const float* __restrict__ W2) {
    int t = blockIdx.x * 256 + threadIdx.x;   // 0..4095
    int n = t >> 5;
    int k = (t & 31) * 4;
    __half2 h0 = __float22half2_rn(make_float2(W2[(k + 0) * 128 + n], W2[(k + 1) * 128 + n]));
    __half2 h1 = __float22half2_rn(make_float2(W2[(k + 2) * 128 + n], W2[(k + 3) * 128 + n]));
    u64 hp = (u64)(*(u32*)&h0) | ((u64)(*(u32*)&h1) << 32);
    *(u64*)(g_w2h + n * BSTRIDE + k * 2) = hp;
}

// ---------------------------------------------------------------------------
// K3: fp16 mma.sync h_two kernel + fused g2 partials. 4096 blocks x 256 thr.
// bid -> j = bid&511, chunk ch=bid>>9: s=ch>>2, q=ch&3; rows = 64 senders.
// Inner loop: per ks, B frags loaded ONCE, then A_hi 8 MMA + A_lo 8 MMA.
// ---------------------------------------------------------------------------
#define S_AHI 0
#define S_ALO 17408
#define S_WHI 34816
#define S_RED 69632
#define SMEM_TWO 73728

__global__ void __launch_bounds__(256, 2)
k_two(const float* __restrict__ h_two,
      const float* __restrict__ b2,
      float* __restrict__ out_two) {
    extern __shared__ char smem[];
    u32 sb = smem_u32(smem);
    int tid = threadIdx.x;
    int lane = tid & 31;
    int w = tid >> 5;

    int j = blockIdx.x & 511;
    int ch = blockIdx.x >> 9;      // 0..7
    int s = ch >> 2;
    int q = ch & 3;
    int ibase = s * 256 + q * 64;

    // stage W2T fp16 image: 2176 uint4
    {
        const uint4* wh = (const uint4*)g_w2h;
        uint4* dh = (uint4*)(smem + S_WHI);
        for (int idx = tid; idx < 2176; idx += 256) dh[idx] = wh[idx];
    }
    // stage A tile: split fp32 -> fp16 hi/lo + column sums
    {
        int rr = tid >> 5;          // 0..7
        int kc = tid & 31;          // k-quad
        const float* base = h_two + (size_t)(ibase + rr) * 65536 + (size_t)j * 128 + kc * 4;
        float4 csum = make_float4(0.f, 0.f, 0.f, 0.f);
#pragma unroll
        for (int it = 0; it < 8; it++) {
            int row = rr + it * 8;
            float4 v = *(const float4*)(base + (size_t)it * 8 * 65536);
            csum.x += v.x; csum.y += v.y; csum.z += v.z; csum.w += v.w;
            u64 hp, lp;
            split4h(v, hp, lp);
            *(u64*)(smem + S_AHI + row * BSTRIDE + kc * 8) = hp;
            *(u64*)(smem + S_ALO + row * BSTRIDE + kc * 8) = lp;
        }
        *(float4*)(smem + S_RED + (rr * 32 + kc) * 16) = csum;
    }
    __syncthreads();

    // g2 partial: threads 0..127 reduce 8 rr-partials for column p=tid
    if (tid < 128) {
        int p = tid;
        float sum = 0.f;
#pragma unroll
        for (int rr = 0; rr < 8; rr++)
            sum += *(const float*)(smem + S_RED + (rr * 32 + (p >> 2)) * 16 + (p & 3) * 4);
        g_g2p[(size_t)q * 131072 + (size_t)s * 65536 + (size_t)j * 128 + p] = sum;
    }

    int mw = w & 1;       // m-block: rows mw*32
    int nw = w >> 1;      // n-block: cols nw*32

    u32 a_off = (u32)((mw * 32 + (lane & 15)) * BSTRIDE + ((lane >> 4) << 4));
    u32 b_off = (u32)((((lane & 7) + ((lane >> 4) << 3)) * BSTRIDE) + (((lane >> 3) & 1) << 4));
    u32 Ah = sb + S_AHI + a_off;
    u32 Al = sb + S_ALO + a_off;
    u32 Bb = sb + S_WHI + (u32)(nw * 32 * BSTRIDE) + b_off;

    float acc[2][4][4];
#pragma unroll
    for (int mi = 0; mi < 2; mi++)
#pragma unroll
        for (int nt = 0; nt < 4; nt++)
#pragma unroll
            for (int c = 0; c < 4; c++) acc[mi][nt][c] = 0.f;

#pragma unroll
    for (int ks = 0; ks < 8; ks++) {
        u32 b0[4], b1[4], a0[4], a1[4];
        ldsm4(b0, Bb + ks * 32);
        ldsm4(b1, Bb + 16 * BSTRIDE + ks * 32);
        // hi pass
        ldsm4(a0, Ah + ks * 32);
        ldsm4(a1, Ah + 16 * BSTRIDE + ks * 32);
        mma16816(acc[0][0], a0, b0);
        mma16816(acc[0][1], a0, b0 + 2);
        mma16816(acc[0][2], a0, b1);
        mma16816(acc[0][3], a0, b1 + 2);
        mma16816(acc[1][0], a1, b0);
        mma16816(acc[1][1], a1, b0 + 2);
        mma16816(acc[1][2], a1, b1);
        mma16816(acc[1][3], a1, b1 + 2);
        // lo pass (reuse a regs)
        ldsm4(a0, Al + ks * 32);
        ldsm4(a1, Al + 16 * BSTRIDE + ks * 32);
        mma16816(acc[0][0], a0, b0);
        mma16816(acc[0][1], a0, b0 + 2);
        mma16816(acc[0][2], a0, b1);
        mma16816(acc[0][3], a0, b1 + 2);
        mma16816(acc[1][0], a1, b0);
        mma16816(acc[1][1], a1, b0 + 2);
        mma16816(acc[1][2], a1, b1);
        mma16816(acc[1][3], a1, b1 + 2);
    }

    // epilogue: out = (A + GAIN*tanh(D + b2)) * RSQRT2; A = hi + lo from smem
    int col0 = nw * 32 + (lane & 3) * 2;
    float2 bz[4];
#pragma unroll
    for (int nt = 0; nt < 4; nt++) bz[nt] = *(const float2*)(b2 + col0 + nt * 8);

#pragma unroll
    for (int mi = 0; mi < 2; mi++) {
#pragma unroll
        for (int half = 0; half < 2; half++) {
            int rt = mw * 32 + mi * 16 + half * 8 + (lane >> 2);
            float* orow = out_two + ((size_t)(ibase + rt) * 512 + j) * 128;
#pragma unroll
            for (int nt = 0; nt < 4; nt++) {
                int c = col0 + nt * 8;
                __half2 hh = *(const __half2*)(smem + S_AHI + rt * BSTRIDE + c * 2);
                __half2 ll = *(const __half2*)(smem + S_ALO + rt * BSTRIDE + c * 2);
                float2 hf = __half22float2(hh);
                float2 lf = __half22float2(ll);
                float d0 = acc[mi][nt][half * 2 + 0] + bz[nt].x;
                float d1 = acc[mi][nt][half * 2 + 1] + bz[nt].y;
                float2 o;
                o.x = (hf.x + lf.x + GAIN * tanh_fast(d0)) * RSQRT2;
                o.y = (hf.y + lf.y + GAIN * tanh_fast(d1)) * RSQRT2;
                *(float2*)(orow + c) = o;
            }
        }
    }
}

// ---------------------------------------------------------------------------
extern "C" void kernel_launch(void* const* d_in, const int* in_sizes, int n_in,
                              void* d_out, int out_size) {
    const float* h_one = (const float*)d_in[0];
    const float* h_two = (const float*)d_in[1];
    const float* W1    = (const float*)d_in[2];
    const float* b1    = (const float*)d_in[3];
    const float* Wg    = (const float*)d_in[4];
    const float* W2    = (const float*)d_in[5];
    const float* b2    = (const float*)d_in[6];

    float* out_one = (float*)d_out;
    float* out_two = (float*)d_out + 512 * 256;

    cudaFuncSetAttribute(k_two, cudaFuncAttributeMaxDynamicSharedMemorySize, SMEM_TWO);

    k_w2prep<<<16, 256>>>(W2);
    k_g1<<<2, 256>>>(h_one);
    k_gtp<<<4, 256>>>(Wg);
    k_two<<<4096, 256, SMEM_TWO>>>(h_two, b2, out_two);
    k_one<<<64, 256>>>(h_one, W1, b1, out_one);
}

// round 9
// speedup vs baseline: 1.2331x; 1.2331x over previous
#include <cuda_runtime.h>
#include <cuda_fp16.h>
#include <cstdint>

// ---------------------------------------------------------------------------
// FermiLayer: N=512 (256 up / 256 dn), SINGLE=256, PAIR=128
// inputs: [0] h_one (512,256) [1] h_two (512,512,128) [2] W1 (512,256)
//         [3] b1 (256) [4] Wg (512,256) [5] W2 (128,128) [6] b2 (128)
// output: [h_one_out | h_two_out] fp32
// k_two: fp16 mma.sync, 2-pass exact-A split (D = A*Wh), 128x128 tiles,
// B-frags shared across hi/lo passes. g2 partials fused into k_two.
// ---------------------------------------------------------------------------

#define GAIN    1.5927812698663017f
#define RSQRT2  0.7071067811865475f
#define INV256  0.00390625f

typedef unsigned long long u64;
typedef unsigned int u32;

// scratch (__device__ globals: allocation-free rule)
__device__ float g_g2p[4 * 512 * 128];   // [(s*2+h)][j][p] partial sums (128 i each)
__device__ float g_g1p[16 * 256];        // g1 partials: [s*8+ck][c], 32 rows each
__device__ float g_gtp[16 * 256];        // gt partials (16 k-chunks)
// W2^T fp16 in padded [n][k] layout (row stride 272B)
__device__ __align__(16) unsigned char g_w2h[35840];

__device__ __forceinline__ float tanh_fast(float x) {
    float y;
    asm("tanh.approx.f32 %0, %1;" : "=f"(y) : "f"(x));
    return y;
}
__device__ __forceinline__ u32 smem_u32(const void* p) {
    u32 a;
    asm("{ .reg .u64 t; cvta.to.shared.u64 t, %1; cvt.u32.u64 %0, t; }" : "=r"(a) : "l"(p));
    return a;
}
__device__ __forceinline__ void ldsm4(u32* r, u32 addr) {
    asm volatile("ldmatrix.sync.aligned.m8n8.x4.shared.b16 {%0,%1,%2,%3}, [%4];"
                 : "=r"(r[0]), "=r"(r[1]), "=r"(r[2]), "=r"(r[3]) : "r"(addr));
}
__device__ __forceinline__ void mma16816(float* c, const u32* a, const u32* b) {
    asm volatile(
        "mma.sync.aligned.m16n8k16.row.col.f32.f16.f16.f32 "
        "{%0,%1,%2,%3}, {%4,%5,%6,%7}, {%8,%9}, {%0,%1,%2,%3};"
        : "+f"(c[0]), "+f"(c[1]), "+f"(c[2]), "+f"(c[3])
        : "r"(a[0]), "r"(a[1]), "r"(a[2]), "r"(a[3]), "r"(b[0]), "r"(b[1]));
}
__device__ __forceinline__ void split2h(float e0, float e1, u32& hp, u32& lp) {
    __half2 h = __float22half2_rn(make_float2(e0, e1));
    float2 hf = __half22float2(h);
    __half2 l = __float22half2_rn(make_float2(e0 - hf.x, e1 - hf.y));
    hp = *(u32*)&h;
    lp = *(u32*)&l;
}
__device__ __forceinline__ void split4h(const float4& v, u64& hp, u64& lp) {
    u32 h0, l0, h1, l1;
    split2h(v.x, v.y, h0, l0);
    split2h(v.z, v.w, h1, l1);
    hp = (u64)h0 | ((u64)h1 << 32);
    lp = (u64)l0 | ((u64)l1 << 32);
}

// ---------------------------------------------------------------------------
// K1a: g1 partials. 16 blocks (2 spins x 8 chunks of 32 rows), 256 threads.
// ---------------------------------------------------------------------------
__global__ void k_g1(const float* __restrict__ h_one) {
    int b = blockIdx.x;
    int s = b >> 3, ck = b & 7;
    int c = threadIdx.x;
    const float* p = h_one + (size_t)(s * 256 + ck * 32) * 256 + c;
    float sum = 0.f;
#pragma unroll 8
    for (int r = 0; r < 32; r++) sum += p[r * 256];
    g_g1p[b * 256 + c] = sum;
}

// ---------------------------------------------------------------------------
// K1b: gt partials. 16 blocks, block q covers k in [q*32, q*32+32).
// Folds g1 combine from g_g1p.
// ---------------------------------------------------------------------------
__global__ void k_gtp(const float* __restrict__ Wg) {
    __shared__ float s_g1[32];
    int q = blockIdx.x;
    int c = threadIdx.x;
    if (c < 32) {
        int kk = q * 32 + c;          // 0..511
        int s = kk >> 8;
        int col = kk & 255;
        float sum = 0.f;
#pragma unroll
        for (int ck = 0; ck < 8; ck++) sum += g_g1p[(s * 8 + ck) * 256 + col];
        s_g1[c] = sum * INV256;
    }
    __syncthreads();
    float acc = 0.f;
#pragma unroll
    for (int kb = 0; kb < 4; kb++) {
        float w[8];
#pragma unroll
        for (int i = 0; i < 8; i++) w[i] = Wg[(q * 32 + kb * 8 + i) * 256 + c];
#pragma unroll
        for (int i = 0; i < 8; i++) acc += s_g1[kb * 8 + i] * w[i];
    }
    g_gtp[q * 256 + c] = acc;
}

// ---------------------------------------------------------------------------
// K2: h_one path. 128 blocks x 256 threads, 4 rows/block.
// Folds g2 partial combine (2 halves/spin) and gt combine (+b1).
// ---------------------------------------------------------------------------
__global__ void __launch_bounds__(256)
k_one(const float* __restrict__ h_one,
      const float* __restrict__ W1,
      const float* __restrict__ b1,
      float* __restrict__ out_one) {
    __shared__ float s_in[2048];   // [k][r], k=0..511, r=0..3
    int tid = threadIdx.x;
    int r0 = blockIdx.x * 4;
#pragma unroll
    for (int i = 0; i < 8; i++) {
        int e = tid + i * 256;     // 0..2047
        int k = e >> 2;
        int r = e & 3;
        int n = r0 + r;
        float v;
        if (k < 256) {
            v = h_one[n * 256 + k];
        } else {
            int sp = (k < 384) ? 0 : 1;
            int p = k - 256 - sp * 128;
            size_t base = (size_t)(sp * 2) * 65536 + (size_t)n * 128 + p;
            v = (g_g2p[base] + g_g2p[base + 65536]) * INV256;
        }
        s_in[k * 4 + r] = v;
    }
    __syncthreads();

    int c = tid;
    float acc[4] = {0.f, 0.f, 0.f, 0.f};
#pragma unroll 4
    for (int kb = 0; kb < 64; kb++) {
        float w[8];
#pragma unroll
        for (int i = 0; i < 8; i++) w[i] = W1[(kb * 8 + i) * 256 + c];
#pragma unroll
        for (int i = 0; i < 8; i++) {
            float4 a = *(const float4*)(s_in + (kb * 8 + i) * 4);
            acc[0] += a.x * w[i];
            acc[1] += a.y * w[i];
            acc[2] += a.z * w[i];
            acc[3] += a.w * w[i];
        }
    }
    float gt = b1[c];
#pragma unroll
    for (int q = 0; q < 16; q++) gt += g_gtp[q * 256 + c];
#pragma unroll
    for (int r = 0; r < 4; r++) {
        float pre = (acc[r] + gt) * RSQRT2;
        out_one[(r0 + r) * 256 + c] = (s_in[c * 4 + r] + GAIN * tanh_fast(pre)) * RSQRT2;
    }
}

// ---------------------------------------------------------------------------
// W2 prep: W2T[n][k] = fp16(W2[k][n]), padded rows (272B stride).
// ---------------------------------------------------------------------------
#define BSTRIDE 272

__global__ void k_w2prep(const float* __restrict__ W2) {
    int t = blockIdx.x * 256 + threadIdx.x;   // 0..4095
    int n = t >> 5;
    int k = (t & 31) * 4;
    __half2 h0 = __float22half2_rn(make_float2(W2[(k + 0) * 128 + n], W2[(k + 1) * 128 + n]));
    __half2 h1 = __float22half2_rn(make_float2(W2[(k + 2) * 128 + n], W2[(k + 3) * 128 + n]));
    u64 hp = (u64)(*(u32*)&h0) | ((u64)(*(u32*)&h1) << 32);
    *(u64*)(g_w2h + n * BSTRIDE + k * 2) = hp;
}

// ---------------------------------------------------------------------------
// K3: fp16 mma.sync h_two kernel + fused g2 partials. 2048 blocks x 256 thr.
// bid -> j = bid&511, ch = bid>>9 (0..3): s = ch>>1, h = ch&1.
// Tile = 128 senders (i = s*256 + h*128 ..) x 128 cols, fixed receiver j.
// Warp = 32m x 64n (mw = w&3, nw = w>>2). Per ks: 4 B ldsm shared by hi/lo.
// ---------------------------------------------------------------------------
#define S_AHI 0
#define S_ALO 34816
#define S_WHI 69632
#define S_RED 104448
#define SMEM_TWO 108544

__global__ void __launch_bounds__(256, 2)
k_two(const float* __restrict__ h_two,
      const float* __restrict__ b2,
      float* __restrict__ out_two) {
    extern __shared__ char smem[];
    u32 sb = smem_u32(smem);
    int tid = threadIdx.x;
    int lane = tid & 31;
    int w = tid >> 5;

    int j = blockIdx.x & 511;
    int ch = blockIdx.x >> 9;      // 0..3
    int s = ch >> 1;
    int h = ch & 1;
    int ibase = s * 256 + h * 128;

    // stage W2T fp16 image: 2176 uint4
    {
        const uint4* wh = (const uint4*)g_w2h;
        uint4* dh = (uint4*)(smem + S_WHI);
        for (int idx = tid; idx < 2176; idx += 256) dh[idx] = wh[idx];
    }
    // stage A tile (128 rows): split fp32 -> fp16 hi/lo + column sums
    {
        int rr = tid >> 5;          // 0..7
        int kc = tid & 31;          // k-quad
        const float* base = h_two + (size_t)(ibase + rr) * 65536 + (size_t)j * 128 + kc * 4;
        float4 csum = make_float4(0.f, 0.f, 0.f, 0.f);
#pragma unroll
        for (int it = 0; it < 16; it++) {
            int row = rr + it * 8;
            float4 v = *(const float4*)(base + (size_t)it * 8 * 65536);
            csum.x += v.x; csum.y += v.y; csum.z += v.z; csum.w += v.w;
            u64 hp, lp;
            split4h(v, hp, lp);
            *(u64*)(smem + S_AHI + row * BSTRIDE + kc * 8) = hp;
            *(u64*)(smem + S_ALO + row * BSTRIDE + kc * 8) = lp;
        }
        *(float4*)(smem + S_RED + (rr * 32 + kc) * 16) = csum;
    }
    __syncthreads();

    // g2 partial: threads 0..127 reduce 8 rr-partials for column p=tid
    if (tid < 128) {
        int p = tid;
        float sum = 0.f;
#pragma unroll
        for (int rr = 0; rr < 8; rr++)
            sum += *(const float*)(smem + S_RED + (rr * 32 + (p >> 2)) * 16 + (p & 3) * 4);
        g_g2p[(size_t)(s * 2 + h) * 65536 + (size_t)j * 128 + p] = sum;
    }

    int mw = w & 3;       // m-block: rows mw*32
    int nw = w >> 2;      // n-block: cols nw*64

    u32 a_off = (u32)((mw * 32 + (lane & 15)) * BSTRIDE + ((lane >> 4) << 4));
    u32 b_off = (u32)((((lane & 7) + ((lane >> 4) << 3)) * BSTRIDE) + (((lane >> 3) & 1) << 4));
    u32 Ah = sb + S_AHI + a_off;
    u32 Al = sb + S_ALO + a_off;
    u32 Bb = sb + S_WHI + (u32)(nw * 64 * BSTRIDE) + b_off;

    float acc[2][8][4];
#pragma unroll
    for (int mi = 0; mi < 2; mi++)
#pragma unroll
        for (int nt = 0; nt < 8; nt++)
#pragma unroll
            for (int c = 0; c < 4; c++) acc[mi][nt][c] = 0.f;

#pragma unroll
    for (int ks = 0; ks < 8; ks++) {
        u32 b[4][4], a0[4], a1[4];
#pragma unroll
        for (int nb = 0; nb < 4; nb++) ldsm4(b[nb], Bb + nb * 16 * BSTRIDE + ks * 32);
        // hi pass
        ldsm4(a0, Ah + ks * 32);
        ldsm4(a1, Ah + 16 * BSTRIDE + ks * 32);
#pragma unroll
        for (int nb = 0; nb < 4; nb++) {
            mma16816(acc[0][nb * 2 + 0], a0, b[nb]);
            mma16816(acc[0][nb * 2 + 1], a0, b[nb] + 2);
            mma16816(acc[1][nb * 2 + 0], a1, b[nb]);
            mma16816(acc[1][nb * 2 + 1], a1, b[nb] + 2);
        }
        // lo pass (reuse a regs)
        ldsm4(a0, Al + ks * 32);
        ldsm4(a1, Al + 16 * BSTRIDE + ks * 32);
#pragma unroll
        for (int nb = 0; nb < 4; nb++) {
            mma16816(acc[0][nb * 2 + 0], a0, b[nb]);
            mma16816(acc[0][nb * 2 + 1], a0, b[nb] + 2);
            mma16816(acc[1][nb * 2 + 0], a1, b[nb]);
            mma16816(acc[1][nb * 2 + 1], a1, b[nb] + 2);
        }
    }

    // epilogue: out = (A + GAIN*tanh(D + b2)) * RSQRT2; A = hi + lo from smem
    int col0 = nw * 64 + (lane & 3) * 2;
    float2 bz[8];
#pragma unroll
    for (int nt = 0; nt < 8; nt++) bz[nt] = *(const float2*)(b2 + col0 + nt * 8);

#pragma unroll
    for (int mi = 0; mi < 2; mi++) {
#pragma unroll
        for (int half = 0; half < 2; half++) {
            int rt = mw * 32 + mi * 16 + half * 8 + (lane >> 2);
            float* orow = out_two + ((size_t)(ibase + rt) * 512 + j) * 128;
#pragma unroll
            for (int nt = 0; nt < 8; nt++) {
                int c = col0 + nt * 8;
                __half2 hh = *(const __half2*)(smem + S_AHI + rt * BSTRIDE + c * 2);
                __half2 ll = *(const __half2*)(smem + S_ALO + rt * BSTRIDE + c * 2);
                float2 hf = __half22float2(hh);
                float2 lf = __half22float2(ll);
                float d0 = acc[mi][nt][half * 2 + 0] + bz[nt].x;
                float d1 = acc[mi][nt][half * 2 + 1] + bz[nt].y;
                float2 o;
                o.x = (hf.x + lf.x + GAIN * tanh_fast(d0)) * RSQRT2;
                o.y = (hf.y + lf.y + GAIN * tanh_fast(d1)) * RSQRT2;
                *(float2*)(orow + c) = o;
            }
        }
    }
}

// ---------------------------------------------------------------------------
extern "C" void kernel_launch(void* const* d_in, const int* in_sizes, int n_in,
                              void* d_out, int out_size) {
    const float* h_one = (const float*)d_in[0];
    const float* h_two = (const float*)d_in[1];
    const float* W1    = (const float*)d_in[2];
    const float* b1    = (const float*)d_in[3];
    const float* Wg    = (const float*)d_in[4];
    const float* W2    = (const float*)d_in[5];
    const float* b2    = (const float*)d_in[6];

    float* out_one = (float*)d_out;
    float* out_two = (float*)d_out + 512 * 256;

    cudaFuncSetAttribute(k_two, cudaFuncAttributeMaxDynamicSharedMemorySize, SMEM_TWO);

    k_w2prep<<<16, 256>>>(W2);
    k_g1<<<16, 256>>>(h_one);
    k_gtp<<<16, 256>>>(Wg);
    k_two<<<2048, 256, SMEM_TWO>>>(h_two, b2, out_two);
    k_one<<<128, 256>>>(h_one, W1, b1, out_one);
}